// round 1
// baseline (speedup 1.0000x reference)
#include <cuda_runtime.h>
#include <cuda_bf16.h>

#define NN 8192
#define IN_DIM 256
#define HID 16
#define KNB 6

#define ROWS_PER_BLOCK 16   // 8 warps * 2 rows
#define CT 512              // column tile
#define SH_STRIDE 20        // floats per column in shared (padded, conflict-free)

__device__ float g_h[NN * HID];
__device__ float g_rowsum[NN];
__device__ int   g_topk_idx[NN * KNB];

// ---------------------------------------------------------------------------
// K1: h = normalize(x @ W^T + b), also zero rowsum for this replay
// ---------------------------------------------------------------------------
__global__ void k_embed(const float* __restrict__ x,
                        const float* __restrict__ W,
                        const float* __restrict__ b) {
    int i = blockIdx.x * blockDim.x + threadIdx.x;
    if (i >= NN) return;
    g_rowsum[i] = 0.0f;

    float acc[HID];
#pragma unroll
    for (int d = 0; d < HID; d++) acc[d] = b[d];

    const float* xr = x + (size_t)i * IN_DIM;
#pragma unroll 4
    for (int k = 0; k < IN_DIM; k++) {
        float xv = xr[k];
#pragma unroll
        for (int d = 0; d < HID; d++)
            acc[d] = fmaf(xv, W[d * IN_DIM + k], acc[d]);
    }
    float ss = 0.0f;
#pragma unroll
    for (int d = 0; d < HID; d++) ss = fmaf(acc[d], acc[d], ss);
    float norm = sqrtf(ss);
    float inv = 1.0f / fmaxf(norm, 1e-12f);
#pragma unroll
    for (int d = 0; d < HID; d++)
        g_h[i * HID + d] = acc[d] * inv;
}

// ---------------------------------------------------------------------------
// Per-lane sorted top-6 insertion (v sorted descending). Caller guards s>v[5].
// Tie-break: keep lower index first (matches jax top_k).
// ---------------------------------------------------------------------------
__device__ __forceinline__ void insert6(float* v, int* ix, float s, int c) {
    float cv = s; int ci = c;
#pragma unroll
    for (int k = 0; k < KNB; k++) {
        bool gt = (cv > v[k]);
        float tv = v[k]; int ti = ix[k];
        if (gt) { v[k] = cv; ix[k] = ci; cv = tv; ci = ti; }
    }
}

// ---------------------------------------------------------------------------
// K2: streaming top-6 per row + symmetric scatter into out / rowsum.
// One warp handles 2 rows; column tiles staged in shared.
// ---------------------------------------------------------------------------
__global__ void k_topk_scatter(float* __restrict__ out) {
    __shared__ float sh[CT * SH_STRIDE];

    int warp = threadIdx.x >> 5;
    int lane = threadIdx.x & 31;
    int r0 = blockIdx.x * ROWS_PER_BLOCK + warp * 2;
    int r1 = r0 + 1;

    float hr0[HID], hr1[HID];
#pragma unroll
    for (int d = 0; d < HID; d++) {
        hr0[d] = g_h[r0 * HID + d];
        hr1[d] = g_h[r1 * HID + d];
    }

    float v0[KNB], v1[KNB];
    int   i0[KNB], i1[KNB];
#pragma unroll
    for (int k = 0; k < KNB; k++) {
        v0[k] = -2.0f; v1[k] = -2.0f;
        i0[k] = 0x7FFFFFFF; i1[k] = 0x7FFFFFFF;
    }

    const int NT = NN / CT;
    for (int tile = 0; tile < NT; tile++) {
        int cbase = tile * CT;
        __syncthreads();
        // cooperative tile load: CT columns * 4 float4 each
        for (int t = threadIdx.x; t < CT * (HID / 4); t += blockDim.x) {
            int c = t >> 2;       // column within tile
            int q = t & 3;        // float4 index within column
            float4 val = ((const float4*)g_h)[(size_t)(cbase + c) * (HID / 4) + q];
            *((float4*)&sh[c * SH_STRIDE + q * 4]) = val;
        }
        __syncthreads();

        for (int cc = lane; cc < CT; cc += 32) {
            int c = cbase + cc;
            const float4* hp = (const float4*)&sh[cc * SH_STRIDE];
            float s0 = 0.0f, s1 = 0.0f;
#pragma unroll
            for (int q = 0; q < 4; q++) {
                float4 a = hp[q];
                s0 = fmaf(a.x, hr0[4*q+0], s0);
                s0 = fmaf(a.y, hr0[4*q+1], s0);
                s0 = fmaf(a.z, hr0[4*q+2], s0);
                s0 = fmaf(a.w, hr0[4*q+3], s0);
                s1 = fmaf(a.x, hr1[4*q+0], s1);
                s1 = fmaf(a.y, hr1[4*q+1], s1);
                s1 = fmaf(a.z, hr1[4*q+2], s1);
                s1 = fmaf(a.w, hr1[4*q+3], s1);
            }
            if (c != r0 && s0 > v0[KNB-1]) insert6(v0, i0, s0, c);
            if (c != r1 && s1 > v1[KNB-1]) insert6(v1, i1, s1, c);
        }
    }

    // merge lanes' top-6 into row top-6 and scatter
#pragma unroll
    for (int rsel = 0; rsel < 2; rsel++) {
        int row = rsel ? r1 : r0;
        float* v = rsel ? v1 : v0;
        int*   ix = rsel ? i1 : i0;
        int ptr = 0;
        for (int t = 0; t < KNB; t++) {
            float bv = (ptr < KNB) ? v[ptr] : -3.0f;
            int   bi = (ptr < KNB) ? ix[ptr] : 0x7FFFFFFF;
#pragma unroll
            for (int off = 16; off; off >>= 1) {
                float ov = __shfl_xor_sync(0xFFFFFFFFu, bv, off);
                int   oi = __shfl_xor_sync(0xFFFFFFFFu, bi, off);
                if (ov > bv || (ov == bv && oi < bi)) { bv = ov; bi = oi; }
            }
            // winner lane owns column bi (columns are lane-strided: c % 32 == lane)
            if ((bi & 31) == lane) ptr++;
            if (lane == t) {
                float half = 0.5f * bv;
                atomicAdd(&out[(size_t)row * NN + bi], half);
                atomicAdd(&out[(size_t)bi * NN + row], half);
                atomicAdd(&g_rowsum[row], half);
                atomicAdd(&g_rowsum[bi], half);
                g_topk_idx[row * KNB + t] = bi;
            }
        }
    }
}

// ---------------------------------------------------------------------------
// K3: in-place row normalization at the sparse nonzeros.
// Unique cell ownership: for reciprocal edge pairs only the lower-index
// endpoint writes (avoids double division).
// ---------------------------------------------------------------------------
__global__ void k_normalize(float* __restrict__ out) {
    int e = blockIdx.x * blockDim.x + threadIdx.x;
    if (e >= NN * KNB) return;
    int i = e / KNB;
    int j = g_topk_idx[e];

    bool recip = false;
#pragma unroll
    for (int t = 0; t < KNB; t++)
        recip |= (g_topk_idx[j * KNB + t] == i);
    if (recip && j < i) return;

    float rsi = g_rowsum[i];
    float rsj = g_rowsum[j];
    float a = out[(size_t)i * NN + j];
    out[(size_t)i * NN + j] = a / (rsi + 1e-8f);
    float c = out[(size_t)j * NN + i];
    out[(size_t)j * NN + i] = c / (rsj + 1e-8f);
}

// ---------------------------------------------------------------------------
extern "C" void kernel_launch(void* const* d_in, const int* in_sizes, int n_in,
                              void* d_out, int out_size) {
    const float* x = (const float*)d_in[0];
    const float* W = (const float*)d_in[1];
    const float* b = (const float*)d_in[2];
    float* out = (float*)d_out;

    cudaMemsetAsync(out, 0, (size_t)NN * NN * sizeof(float));
    k_embed<<<NN / 256, 256>>>(x, W, b);
    k_topk_scatter<<<NN / ROWS_PER_BLOCK, 256>>>(out);
    k_normalize<<<(NN * KNB + 255) / 256, 256>>>(out);
}

// round 2
// speedup vs baseline: 1.0740x; 1.0740x over previous
#include <cuda_runtime.h>
#include <cuda_bf16.h>

#define NN 8192
#define IN_DIM 256
#define HID 16
#define KNB 6

// ---- k_topk config: 4 warps/block, 4 rows/warp -> 16 rows/block, 512 blocks
#define TPB_TOPK 128
#define WARPS_TOPK 4
#define ROWS_PER_WARP 4
#define ROWS_PER_BLOCK (WARPS_TOPK * ROWS_PER_WARP)
#define CT 512
#define SH_STRIDE 20  // floats per column (padded; LDS.128 conflict-free)

__device__ float g_h[NN * HID];
__device__ float g_rowsum[NN];
__device__ int   g_topk_idx[NN * KNB];
__device__ float g_topk_val[NN * KNB];

// ---------------------------------------------------------------------------
// packed f32x2 helpers (sm_100+)
// ---------------------------------------------------------------------------
__device__ __forceinline__ unsigned long long pack2(float a, float b) {
    unsigned long long r;
    asm("mov.b64 %0, {%1,%2};" : "=l"(r) : "f"(a), "f"(b));
    return r;
}
__device__ __forceinline__ unsigned long long ffma2(unsigned long long a,
                                                    unsigned long long b,
                                                    unsigned long long c) {
    unsigned long long d;
    asm("fma.rn.f32x2 %0, %1, %2, %3;" : "=l"(d) : "l"(a), "l"(b), "l"(c));
    return d;
}
__device__ __forceinline__ void unpack2(unsigned long long v, float& x, float& y) {
    asm("mov.b64 {%0,%1}, %2;" : "=f"(x), "=f"(y) : "l"(v));
}

// ---------------------------------------------------------------------------
// K1: warp-per-row h = normalize(x @ W^T + b); also zeroes rowsum.
// ---------------------------------------------------------------------------
__global__ __launch_bounds__(256) void k_embed(const float* __restrict__ x,
                                               const float* __restrict__ W,
                                               const float* __restrict__ b) {
    __shared__ float sW[HID * IN_DIM];  // 16 KB
    // cooperative W load
    for (int t = threadIdx.x; t < HID * IN_DIM / 4; t += blockDim.x)
        ((float4*)sW)[t] = ((const float4*)W)[t];
    __syncthreads();

    int warp = threadIdx.x >> 5;
    int lane = threadIdx.x & 31;
    int row = blockIdx.x * 8 + warp;

    float acc[HID];
#pragma unroll
    for (int d = 0; d < HID; d++) acc[d] = 0.0f;

    const float* xr = x + (size_t)row * IN_DIM;
#pragma unroll
    for (int q = 0; q < 8; q++) {
        float xv = xr[lane + 32 * q];
#pragma unroll
        for (int d = 0; d < HID; d++)
            acc[d] = fmaf(xv, sW[d * IN_DIM + lane + 32 * q], acc[d]);
    }

    // butterfly reduce: end state = lane l holds dim (l & 15)
#pragma unroll
    for (int d = 0; d < HID; d++)
        acc[d] += __shfl_xor_sync(0xFFFFFFFFu, acc[d], 16);
#pragma unroll
    for (int d = 0; d < 8; d++) {
        bool hi = (lane & 8);
        float keep = hi ? acc[d + 8] : acc[d];
        float send = hi ? acc[d] : acc[d + 8];
        acc[d] = keep + __shfl_xor_sync(0xFFFFFFFFu, send, 8);
    }
#pragma unroll
    for (int d = 0; d < 4; d++) {
        bool hi = (lane & 4);
        float keep = hi ? acc[d + 4] : acc[d];
        float send = hi ? acc[d] : acc[d + 4];
        acc[d] = keep + __shfl_xor_sync(0xFFFFFFFFu, send, 4);
    }
#pragma unroll
    for (int d = 0; d < 2; d++) {
        bool hi = (lane & 2);
        float keep = hi ? acc[d + 2] : acc[d];
        float send = hi ? acc[d] : acc[d + 2];
        acc[d] = keep + __shfl_xor_sync(0xFFFFFFFFu, send, 2);
    }
    {
        bool hi = (lane & 1);
        float keep = hi ? acc[1] : acc[0];
        float send = hi ? acc[0] : acc[1];
        acc[0] = keep + __shfl_xor_sync(0xFFFFFFFFu, send, 1);
    }
    float val = acc[0] + b[lane & 15];

    // sum of squares within each 16-lane half (each half holds all 16 dims)
    float ss = val * val;
#pragma unroll
    for (int off = 1; off < 16; off <<= 1)
        ss += __shfl_xor_sync(0xFFFFFFFFu, ss, off);

    float inv = 1.0f / fmaxf(sqrtf(ss), 1e-12f);
    if (lane < 16) g_h[row * HID + lane] = val * inv;
    if (lane == 16) g_rowsum[row] = 0.0f;
}

// ---------------------------------------------------------------------------
// sorted top-6 insertion (descending); caller guards s > v[5]
// ---------------------------------------------------------------------------
__device__ __forceinline__ void insert6(float* v, int* ix, float s, int c) {
    float cv = s; int ci = c;
#pragma unroll
    for (int k = 0; k < KNB; k++) {
        bool gt = (cv > v[k]);
        float tv = v[k]; int ti = ix[k];
        if (gt) { v[k] = cv; ix[k] = ci; cv = tv; ci = ti; }
    }
}

// ---------------------------------------------------------------------------
// K2: streaming top-6 per row (4 rows/warp, f32x2), store compact topk +
// accumulate rowsum. Does NOT touch the dense output.
// ---------------------------------------------------------------------------
__global__ __launch_bounds__(TPB_TOPK) void k_topk(void) {
    __shared__ float sh[CT * SH_STRIDE];  // 40 KB

    int warp = threadIdx.x >> 5;
    int lane = threadIdx.x & 31;
    int rbase = blockIdx.x * ROWS_PER_BLOCK + warp * ROWS_PER_WARP;

    // packed row embeddings: hp01[d] = (h[r0][d], h[r1][d]); hp23 likewise
    unsigned long long hp01[HID], hp23[HID];
#pragma unroll
    for (int d = 0; d < HID; d++) {
        hp01[d] = pack2(g_h[(rbase + 0) * HID + d], g_h[(rbase + 1) * HID + d]);
        hp23[d] = pack2(g_h[(rbase + 2) * HID + d], g_h[(rbase + 3) * HID + d]);
    }

    float v[ROWS_PER_WARP][KNB];
    int   ix[ROWS_PER_WARP][KNB];
#pragma unroll
    for (int r = 0; r < ROWS_PER_WARP; r++)
#pragma unroll
        for (int k = 0; k < KNB; k++) { v[r][k] = -2.0f; ix[r][k] = 0x7FFFFFFF; }

    const int NT = NN / CT;
    for (int tile = 0; tile < NT; tile++) {
        int cbase = tile * CT;
        __syncthreads();
        for (int t = threadIdx.x; t < CT * (HID / 4); t += TPB_TOPK) {
            int c = t >> 2;
            int q = t & 3;
            float4 val = ((const float4*)g_h)[(size_t)(cbase + c) * (HID / 4) + q];
            *((float4*)&sh[c * SH_STRIDE + q * 4]) = val;
        }
        __syncthreads();

        for (int cc = lane; cc < CT; cc += 32) {
            int c = cbase + cc;
            const float4* hp = (const float4*)&sh[cc * SH_STRIDE];
            unsigned long long s01 = 0ull, s23 = 0ull;
#pragma unroll
            for (int q = 0; q < 4; q++) {
                float4 a = hp[q];
                unsigned long long ax = pack2(a.x, a.x);
                s01 = ffma2(ax, hp01[4 * q + 0], s01);
                s23 = ffma2(ax, hp23[4 * q + 0], s23);
                unsigned long long ay = pack2(a.y, a.y);
                s01 = ffma2(ay, hp01[4 * q + 1], s01);
                s23 = ffma2(ay, hp23[4 * q + 1], s23);
                unsigned long long az = pack2(a.z, a.z);
                s01 = ffma2(az, hp01[4 * q + 2], s01);
                s23 = ffma2(az, hp23[4 * q + 2], s23);
                unsigned long long aw = pack2(a.w, a.w);
                s01 = ffma2(aw, hp01[4 * q + 3], s01);
                s23 = ffma2(aw, hp23[4 * q + 3], s23);
            }
            float s0, s1, s2, s3;
            unpack2(s01, s0, s1);
            unpack2(s23, s2, s3);
            if (c != rbase + 0 && s0 > v[0][KNB - 1]) insert6(v[0], ix[0], s0, c);
            if (c != rbase + 1 && s1 > v[1][KNB - 1]) insert6(v[1], ix[1], s1, c);
            if (c != rbase + 2 && s2 > v[2][KNB - 1]) insert6(v[2], ix[2], s2, c);
            if (c != rbase + 3 && s3 > v[3][KNB - 1]) insert6(v[3], ix[3], s3, c);
        }
    }

    // merge lanes' top-6 per row, store compact lists + rowsum atomics
#pragma unroll
    for (int r = 0; r < ROWS_PER_WARP; r++) {
        int row = rbase + r;
        int ptr = 0;
        for (int t = 0; t < KNB; t++) {
            float bv = (ptr < KNB) ? v[r][ptr] : -3.0f;
            int   bi = (ptr < KNB) ? ix[r][ptr] : 0x7FFFFFFF;
#pragma unroll
            for (int off = 16; off; off >>= 1) {
                float ov = __shfl_xor_sync(0xFFFFFFFFu, bv, off);
                int   oi = __shfl_xor_sync(0xFFFFFFFFu, bi, off);
                if (ov > bv || (ov == bv && oi < bi)) { bv = ov; bi = oi; }
            }
            if ((bi & 31) == lane) ptr++;  // owner advances (cols lane-strided)
            if (lane == t) {
                float half = 0.5f * bv;
                atomicAdd(&g_rowsum[row], half);
                atomicAdd(&g_rowsum[bi], half);
                g_topk_idx[row * KNB + t] = bi;
                g_topk_val[row * KNB + t] = bv;
            }
        }
    }
}

// ---------------------------------------------------------------------------
// K3: write sparse cells into the zeroed dense output.
// cell(i,j) = cell(j,i) numerator = 0.5*(v_ij + v_ji[if reciprocal]);
// ownership: for reciprocal pairs only the lower-index endpoint writes.
// ---------------------------------------------------------------------------
__global__ void k_write(float* __restrict__ out) {
    int e = blockIdx.x * blockDim.x + threadIdx.x;
    if (e >= NN * KNB) return;
    int i = e / KNB;
    int j = g_topk_idx[e];
    float vij = g_topk_val[e];

    float vji = 0.0f;
    bool recip = false;
#pragma unroll
    for (int t = 0; t < KNB; t++) {
        if (g_topk_idx[j * KNB + t] == i) { recip = true; vji = g_topk_val[j * KNB + t]; }
    }
    if (recip && j < i) return;  // unique writer per unordered pair

    float num = 0.5f * (vij + vji);
    out[(size_t)i * NN + j] = num / (g_rowsum[i] + 1e-8f);
    out[(size_t)j * NN + i] = num / (g_rowsum[j] + 1e-8f);
}

// ---------------------------------------------------------------------------
extern "C" void kernel_launch(void* const* d_in, const int* in_sizes, int n_in,
                              void* d_out, int out_size) {
    const float* x = (const float*)d_in[0];
    const float* W = (const float*)d_in[1];
    const float* b = (const float*)d_in[2];
    float* out = (float*)d_out;

    // lazy side-stream for overlapping the 256 MB zero-fill with compute
    static cudaStream_t s_side = nullptr;
    static cudaEvent_t evF = nullptr, evJ = nullptr;
    if (!s_side) {
        cudaStreamCreateWithFlags(&s_side, cudaStreamNonBlocking);
        cudaEventCreateWithFlags(&evF, cudaEventDisableTiming);
        cudaEventCreateWithFlags(&evJ, cudaEventDisableTiming);
    }

    cudaEventRecord(evF, 0);
    cudaStreamWaitEvent(s_side, evF, 0);
    cudaMemsetAsync(out, 0, (size_t)NN * NN * sizeof(float), s_side);
    cudaEventRecord(evJ, s_side);

    k_embed<<<NN / 8, 256>>>(x, W, b);
    k_topk<<<NN / ROWS_PER_BLOCK, TPB_TOPK>>>();

    cudaStreamWaitEvent(0, evJ, 0);
    k_write<<<(NN * KNB + 255) / 256, 256>>>(out);
}